// round 15
// baseline (speedup 1.0000x reference)
#include <cuda_runtime.h>
#include <math.h>

#define BATCH 4
#define NA 120000
#define PRE 12000
#define POST 2000
#define CAP 16384
#define PCAP (CAP + CAP / 16)          // padded physical size (17-stride tiles)
#define PHYS(i) ((i) + ((i) >> 4))     // logical -> physical index (u64 slots)
#define NBUCK 4096

// ---------------- scratch (static __device__, no allocation) ----------------
__device__ float  g_scores[BATCH * NA];
__device__ float4 g_sorted[BATCH * PRE];

// ---------------- XLA:CPU GenerateVF32Exp bit-exact replica ----------------
// DO NOT TOUCH — rel_err == 0.0 with this exact arithmetic (R9/R12/R13).
__device__ __forceinline__ float xla_cpu_expf(float xin) {
    float xc = fminf(fmaxf(xin, -88.3762626647949f), 88.3762626647950f);
    float fx = floorf(fmaf(xc, 1.44269504088896341f, 0.5f));
    float tmp = __fmul_rn(0.693359375f, fx);
    float zz  = __fmul_rn(-2.12194440e-4f, fx);
    float x   = __fsub_rn(xc, tmp);
    x = __fsub_rn(x, zz);
    float z2 = __fmul_rn(x, x);
    float y = 1.9875691500E-4f;
    y = fmaf(y, x, 1.3981999507E-3f);
    y = fmaf(y, x, 8.3334519073E-3f);
    y = fmaf(y, x, 4.1665795894E-2f);
    y = fmaf(y, x, 1.6666665459E-1f);
    y = fmaf(y, x, 5.0000001201E-1f);
    y = fmaf(y, z2, x);
    y = __fadd_rn(1.0f, y);
    int emm0 = ((int)fx + 127) << 23;
    float scale = __int_as_float(emm0);
    return fmaxf(__fmul_rn(y, scale), xin);
}

// ---------------- K1: scores (FROZEN — bit-exact vs reference) ----------------
__global__ void score_kernel(const float4* __restrict__ labels) {
    int i = blockIdx.x * blockDim.x + threadIdx.x;
    if (i < BATCH * NA) {
        float4 l = labels[i];
        float m = fmaxf(fmaxf(l.x, l.y), fmaxf(l.z, l.w));
        float f0 = xla_cpu_expf(__fsub_rn(l.x, m));
        float f1 = xla_cpu_expf(__fsub_rn(l.y, m));
        float f2 = xla_cpu_expf(__fsub_rn(l.z, m));
        float f3 = xla_cpu_expf(__fsub_rn(l.w, m));
        float s  = __fadd_rn(__fadd_rn(f0, f2), __fadd_rn(f1, f3));
        g_scores[i] = __fdiv_rn(fmaxf(fmaxf(f1, f2), f3), s);
    }
}

// ---------------- K2: per-batch radix-select + bitonic sort + gather ----------------
__device__ __forceinline__ void suffix_scan4096(unsigned* cnt, int tid) {
    for (int off = 1; off < NBUCK; off <<= 1) {
        unsigned v[NBUCK / 1024];
#pragma unroll
        for (int k = 0; k < NBUCK / 1024; k++) {
            int i = tid + k * 1024;
            unsigned x = cnt[i];
            if (i + off < NBUCK) x += cnt[i + off];
            v[k] = x;
        }
        __syncthreads();
#pragma unroll
        for (int k = 0; k < NBUCK / 1024; k++) cnt[tid + k * 1024] = v[k];
        __syncthreads();
    }
}

#define CE64(a, b, d)                                              \
    do {                                                           \
        unsigned long long _ta = (a), _tb = (b);                   \
        if ((d) ? (_ta < _tb) : (_ta > _tb)) { (a) = _tb; (b) = _ta; } \
    } while (0)

__global__ void __launch_bounds__(1024, 1) select_kernel(const float4* __restrict__ boxes) {
    extern __shared__ unsigned char smem_raw[];
    unsigned long long* sbuf = reinterpret_cast<unsigned long long*>(smem_raw);
    unsigned* cnt = reinterpret_cast<unsigned*>(smem_raw + (size_t)PCAP * 8);
    __shared__ int sh_b1, sh_need, sh_b2, sh_count;

    const int b = blockIdx.x;
    const int tid = threadIdx.x;
    const int lane = tid & 31;
    const float* sc = g_scores + b * NA;
    const int NIT = (NA + 1023) / 1024;

    // ---- pass 1: histogram of top 12 bits ----
    for (int i = tid; i < NBUCK; i += 1024) cnt[i] = 0;
    __syncthreads();
    for (int it = 0; it < NIT; it++) {
        int a = it * 1024 + tid;
        unsigned bucket = 0xFFFFFFFFu;
        if (a < NA) bucket = __float_as_uint(sc[a]) >> 20;
        unsigned mask = __match_any_sync(0xFFFFFFFFu, bucket);
        int leader = __ffs(mask) - 1;
        if (bucket != 0xFFFFFFFFu && lane == leader)
            atomicAdd(&cnt[bucket], (unsigned)__popc(mask));
    }
    __syncthreads();
    suffix_scan4096(cnt, tid);
#pragma unroll
    for (int k = 0; k < NBUCK / 1024; k++) {
        int i = tid + k * 1024;
        unsigned s = cnt[i];
        unsigned nxt = (i + 1 < NBUCK) ? cnt[i + 1] : 0u;
        if (s >= PRE && nxt < PRE) { sh_b1 = i; sh_need = PRE - (int)nxt; }
    }
    __syncthreads();
    int b1 = sh_b1;
    int need = sh_need;
    __syncthreads();

    // ---- pass 2: within bucket b1, histogram of next 12 bits ----
    for (int i = tid; i < NBUCK; i += 1024) cnt[i] = 0;
    __syncthreads();
    for (int it = 0; it < NIT; it++) {
        int a = it * 1024 + tid;
        unsigned bucket = 0xFFFFFFFFu;
        if (a < NA) {
            unsigned u = __float_as_uint(sc[a]);
            if ((int)(u >> 20) == b1) bucket = (u >> 8) & 0xFFFu;
        }
        unsigned mask = __match_any_sync(0xFFFFFFFFu, bucket);
        int leader = __ffs(mask) - 1;
        if (bucket != 0xFFFFFFFFu && lane == leader)
            atomicAdd(&cnt[bucket], (unsigned)__popc(mask));
    }
    __syncthreads();
    suffix_scan4096(cnt, tid);
#pragma unroll
    for (int k = 0; k < NBUCK / 1024; k++) {
        int i = tid + k * 1024;
        unsigned s = cnt[i];
        unsigned nxt = (i + 1 < NBUCK) ? cnt[i + 1] : 0u;
        if (s >= (unsigned)need && nxt < (unsigned)need) sh_b2 = i;
    }
    if (tid == 0) sh_count = 0;
    __syncthreads();
    unsigned P = ((unsigned)b1 << 12) | (unsigned)sh_b2;

    // ---- compact survivors into padded smem as 64-bit keys (warp-aggregated) ----
    for (int it = 0; it < NIT; it++) {
        int a = it * 1024 + tid;
        unsigned u = 0;
        bool keep = false;
        if (a < NA) {
            u = __float_as_uint(sc[a]);
            keep = ((u >> 8) >= P);
        }
        unsigned bm = __ballot_sync(0xFFFFFFFFu, keep);
        if (keep) {
            int leader = __ffs(bm) - 1;
            int base;
            if (lane == leader) base = atomicAdd(&sh_count, __popc(bm));
            base = __shfl_sync(bm, base, leader);
            int pos = base + __popc(bm & ((1u << lane) - 1u));
            if (pos < CAP)
                sbuf[PHYS(pos)] = ((unsigned long long)u << 32) | (unsigned)(~a);
        }
    }
    __syncthreads();
    int total = min(sh_count, CAP);
    for (int i = total + tid; i < CAP; i += 1024) sbuf[PHYS(i)] = 0ULL;
    __syncthreads();

    // ---- bitonic sort descending, register-fused, bank-conflict-free ----
    {
        int base = tid * 16;
        int pbase = 17 * tid;
        unsigned long long v[16];
#pragma unroll
        for (int e = 0; e < 16; e++) v[e] = sbuf[pbase + e];
#pragma unroll
        for (int k2 = 2; k2 <= 16; k2 <<= 1) {
#pragma unroll
            for (int j = k2 >> 1; j >= 1; j >>= 1) {
#pragma unroll
                for (int e = 0; e < 16; e++) {
                    int x = e ^ j;
                    if (x > e) {
                        bool d = (k2 == 16) ? ((base & 16) == 0)
                                            : ((e & k2) == 0);
                        CE64(v[e], v[x], d);
                    }
                }
            }
        }
#pragma unroll
        for (int e = 0; e < 16; e++) sbuf[pbase + e] = v[e];
    }
    __syncthreads();

    for (unsigned k = 32; k <= CAP; k <<= 1) {
        for (unsigned j = k >> 1; j >= 16; j >>= 1) {
            for (unsigned i = tid; i < CAP; i += 1024) {
                unsigned ixj = i ^ j;
                if (ixj > i) {
                    unsigned pi = PHYS(i), pj = PHYS(ixj);
                    unsigned long long va = sbuf[pi], vb = sbuf[pj];
                    bool d = ((i & k) == 0);
                    if (d ? (va < vb) : (va > vb)) {
                        sbuf[pi] = vb;
                        sbuf[pj] = va;
                    }
                }
            }
            __syncthreads();
        }
        {
            int base = tid * 16;
            int pbase = 17 * tid;
            bool d = (((unsigned)base & k) == 0);
            unsigned long long v[16];
#pragma unroll
            for (int e = 0; e < 16; e++) v[e] = sbuf[pbase + e];
#pragma unroll
            for (int j2 = 8; j2 >= 1; j2 >>= 1) {
#pragma unroll
                for (int e = 0; e < 16; e++) {
                    int x = e ^ j2;
                    if (x > e) CE64(v[e], v[x], d);
                }
            }
#pragma unroll
            for (int e = 0; e < 16; e++) sbuf[pbase + e] = v[e];
        }
        __syncthreads();
    }

    // ---- gather top PRE boxes ----
    const float4* bx = boxes + (size_t)b * NA;
    for (int r = tid; r < PRE; r += 1024) {
        unsigned a = ~(unsigned)(sbuf[PHYS(r)] & 0xFFFFFFFFu);
        g_sorted[b * PRE + r] = bx[a];
    }
}

// ---------------- exact area (reference arithmetic) ----------------
__device__ __forceinline__ float area_f(float4 a) {
    return __fmul_rn(__fsub_rn(a.z, a.x), __fsub_rn(a.w, a.y));
}

// ---------------- exact IoU decision with precomputed exact areas ----------------
// div_rn(inter/denom) > 0.7f <=> (double)inter >= (23488103/2^25)*(double)denom
// (25x24-bit f64 product exact; midpoint tie rounds to even successor > 0.7f).
__device__ __forceinline__ bool iou_gt2(float4 a, float aa, float4 b, float ab) {
    const double MID = 23488103.0 / 33554432.0;
    float iy1 = fmaxf(a.x, b.x);
    float ix1 = fmaxf(a.y, b.y);
    float iy2 = fminf(a.z, b.z);
    float ix2 = fminf(a.w, b.w);
    float ih = fmaxf(__fsub_rn(iy2, iy1), 0.f);
    float iw = fmaxf(__fsub_rn(ix2, ix1), 0.f);
    float inter = __fmul_rn(ih, iw);
    float denom = fmaxf(__fsub_rn(__fadd_rn(aa, ab), inter), 1e-8f);
    return (double)inter >= MID * (double)denom;
}

// Conservative prefilter: IoU <= min(A,B)/max(A,B). If min < 0.69*max, the
// reference's IoU cannot exceed 0.7f (1.4% margin >> fp noise) -> safe skip.
__device__ __forceinline__ bool area_pass(float aa, float ab) {
    return fminf(aa, ab) >= 0.69f * fmaxf(aa, ab);
}

// ---------------- K3: chunked lazy greedy NMS ----------------
// Selection function proven bit-identical to the literal transliteration.
// R15 fix: parallel-phase loop iterates on a UNIFORM block index so the
// intra-loop __any_sync is executed by all 32 lanes every iteration
// (R14 deadlocked: lane-dependent trip count + full-mask collective).
__global__ void __launch_bounds__(1024, 1) nms_kernel(float* __restrict__ out) {
    const int b = blockIdx.x;
    const int tid = threadIdx.x;
    const int wid = tid >> 5;
    const int lane = tid & 31;
    const float4* sb = g_sorted + b * PRE;
    float* ob = out + (size_t)b * POST * 4;

    __shared__ float4 sel[POST];
    __shared__ float selarea[POST];
    __shared__ float4 cand[2][32];
    __shared__ unsigned killed_w[32];
    __shared__ int sh_nsel;

    if (tid < 32) cand[0][tid] = sb[tid];
    if (tid == 0) sh_nsel = 0;
    __syncthreads();
    int nsel = 0;

    const int NCH = PRE / 32;  // 375, PRE % 32 == 0
    for (int ch = 0; ch < NCH && nsel < POST; ch++) {
        int cur = ch & 1, nxt = cur ^ 1;

        // prefetch next chunk (warp 1) — overlaps with parallel phase
        if (wid == 1) {
            int j1 = (ch + 1) * 32;
            if (j1 < PRE) cand[nxt][lane] = sb[j1 + lane];
        }

        // parallel phase: warp w owns candidate w; lanes stride sel list.
        // UNIFORM trip count: i0 advances identically on all lanes.
        {
            float4 myc = cand[cur][wid];
            float mya = area_f(myc);
            bool killed = false;
            for (int i0 = 0; i0 < nsel; i0 += 32) {
                int i = i0 + lane;
                if (i < nsel) {
                    float sa = selarea[i];
                    if (area_pass(mya, sa) && iou_gt2(myc, mya, sel[i], sa))
                        killed = true;
                }
                if (__any_sync(0xFFFFFFFFu, killed)) break;
            }
            killed = __any_sync(0xFFFFFFFFu, killed);
            if (lane == 0) killed_w[wid] = killed ? 1u : 0u;
        }
        __syncthreads();

        // resolve phase (warp 0): build supp mask, pick/suppress in order
        if (tid < 32) {
            unsigned supp = __ballot_sync(0xFFFFFFFFu, killed_w[tid] != 0u);
            float4 myc = cand[cur][tid];
            float mya = area_f(myc);
            unsigned live = ~supp;
            int ns = nsel;
            while (live != 0u && ns < POST) {
                int c = __ffs(live) - 1;
                float4 cb = cand[cur][c];          // smem broadcast
                float ca = __shfl_sync(0xFFFFFFFFu, mya, c);
                live &= ~(1u << c);
                bool kill = ((live >> tid) & 1u) && area_pass(mya, ca) &&
                            iou_gt2(myc, mya, cb, ca);
                live &= ~__ballot_sync(0xFFFFFFFFu, kill);
                if (tid == c) { sel[ns] = myc; selarea[ns] = mya; }
                ns++;
            }
            if (tid == 0) sh_nsel = ns;
        }
        __syncthreads();
        nsel = sh_nsel;
    }

    // final write-out: clamped selected rows, zeros after exhaustion
    for (int r = tid; r < POST; r += 1024) {
        float4 v = make_float4(0.f, 0.f, 0.f, 0.f);
        if (r < nsel) v = sel[r];
        v.x = fminf(fmaxf(v.x, 0.f), 1.f);
        v.y = fminf(fmaxf(v.y, 0.f), 1.f);
        v.z = fminf(fmaxf(v.z, 0.f), 1.f);
        v.w = fminf(fmaxf(v.w, 0.f), 1.f);
        reinterpret_cast<float4*>(ob)[r] = v;
    }
}

// ---------------- launcher ----------------
extern "C" void kernel_launch(void* const* d_in, const int* in_sizes, int n_in,
                              void* d_out, int out_size) {
    const float4* boxes = (const float4*)d_in[0];   // [B, A, 4] f32
    const float4* labels = (const float4*)d_in[1];  // [B, A, 4] f32
    float* out = (float*)d_out;                     // [B, POST, 4] f32

    size_t smem = (size_t)PCAP * 8 + (size_t)NBUCK * 4;
    cudaFuncSetAttribute(select_kernel, cudaFuncAttributeMaxDynamicSharedMemorySize,
                         (int)smem);

    score_kernel<<<(BATCH * NA + 255) / 256, 256>>>(labels);
    select_kernel<<<BATCH, 1024, smem>>>(boxes);
    nms_kernel<<<BATCH, 1024>>>(out);
}

// round 17
// speedup vs baseline: 1.0923x; 1.0923x over previous
#include <cuda_runtime.h>
#include <math.h>

#define BATCH 4
#define NA 120000
#define PRE 12000
#define POST 2000
#define CAP 16384
#define PCAP (CAP + CAP / 16)          // padded physical size (17-stride tiles)
#define PHYS(i) ((i) + ((i) >> 4))     // logical -> physical index (u64 slots)
#define NBUCK 4096

// ---------------- scratch (static __device__, no allocation) ----------------
__device__ float  g_scores[BATCH * NA];
__device__ float4 g_sorted[BATCH * PRE];

// ---------------- XLA:CPU GenerateVF32Exp bit-exact replica ----------------
// DO NOT TOUCH — rel_err == 0.0 with this exact arithmetic (R9/R12/R13/R15).
__device__ __forceinline__ float xla_cpu_expf(float xin) {
    float xc = fminf(fmaxf(xin, -88.3762626647949f), 88.3762626647950f);
    float fx = floorf(fmaf(xc, 1.44269504088896341f, 0.5f));
    float tmp = __fmul_rn(0.693359375f, fx);
    float zz  = __fmul_rn(-2.12194440e-4f, fx);
    float x   = __fsub_rn(xc, tmp);
    x = __fsub_rn(x, zz);
    float z2 = __fmul_rn(x, x);
    float y = 1.9875691500E-4f;
    y = fmaf(y, x, 1.3981999507E-3f);
    y = fmaf(y, x, 8.3334519073E-3f);
    y = fmaf(y, x, 4.1665795894E-2f);
    y = fmaf(y, x, 1.6666665459E-1f);
    y = fmaf(y, x, 5.0000001201E-1f);
    y = fmaf(y, z2, x);
    y = __fadd_rn(1.0f, y);
    int emm0 = ((int)fx + 127) << 23;
    float scale = __int_as_float(emm0);
    return fmaxf(__fmul_rn(y, scale), xin);
}

// ---------------- K1: scores (FROZEN — bit-exact vs reference) ----------------
__global__ void score_kernel(const float4* __restrict__ labels) {
    int i = blockIdx.x * blockDim.x + threadIdx.x;
    if (i < BATCH * NA) {
        float4 l = labels[i];
        float m = fmaxf(fmaxf(l.x, l.y), fmaxf(l.z, l.w));
        float f0 = xla_cpu_expf(__fsub_rn(l.x, m));
        float f1 = xla_cpu_expf(__fsub_rn(l.y, m));
        float f2 = xla_cpu_expf(__fsub_rn(l.z, m));
        float f3 = xla_cpu_expf(__fsub_rn(l.w, m));
        float s  = __fadd_rn(__fadd_rn(f0, f2), __fadd_rn(f1, f3));
        g_scores[i] = __fdiv_rn(fmaxf(fmaxf(f1, f2), f3), s);
    }
}

// ---------------- K2: per-batch radix-select + bitonic sort + gather ----------------
__device__ __forceinline__ void suffix_scan4096(unsigned* cnt, int tid) {
    for (int off = 1; off < NBUCK; off <<= 1) {
        unsigned v[NBUCK / 1024];
#pragma unroll
        for (int k = 0; k < NBUCK / 1024; k++) {
            int i = tid + k * 1024;
            unsigned x = cnt[i];
            if (i + off < NBUCK) x += cnt[i + off];
            v[k] = x;
        }
        __syncthreads();
#pragma unroll
        for (int k = 0; k < NBUCK / 1024; k++) cnt[tid + k * 1024] = v[k];
        __syncthreads();
    }
}

#define CE64(a, b, d)                                              \
    do {                                                           \
        unsigned long long _ta = (a), _tb = (b);                   \
        if ((d) ? (_ta < _tb) : (_ta > _tb)) { (a) = _tb; (b) = _ta; } \
    } while (0)

__global__ void __launch_bounds__(1024, 1) select_kernel(const float4* __restrict__ boxes) {
    extern __shared__ unsigned char smem_raw[];
    unsigned long long* sbuf = reinterpret_cast<unsigned long long*>(smem_raw);
    unsigned* cnt = reinterpret_cast<unsigned*>(smem_raw + (size_t)PCAP * 8);
    __shared__ int sh_b1, sh_need, sh_b2, sh_count;

    const int b = blockIdx.x;
    const int tid = threadIdx.x;
    const int lane = tid & 31;
    const float* sc = g_scores + b * NA;
    const int NIT = (NA + 1023) / 1024;

    // ---- pass 1: histogram of top 12 bits ----
    for (int i = tid; i < NBUCK; i += 1024) cnt[i] = 0;
    __syncthreads();
    for (int it = 0; it < NIT; it++) {
        int a = it * 1024 + tid;
        unsigned bucket = 0xFFFFFFFFu;
        if (a < NA) bucket = __float_as_uint(sc[a]) >> 20;
        unsigned mask = __match_any_sync(0xFFFFFFFFu, bucket);
        int leader = __ffs(mask) - 1;
        if (bucket != 0xFFFFFFFFu && lane == leader)
            atomicAdd(&cnt[bucket], (unsigned)__popc(mask));
    }
    __syncthreads();
    suffix_scan4096(cnt, tid);
#pragma unroll
    for (int k = 0; k < NBUCK / 1024; k++) {
        int i = tid + k * 1024;
        unsigned s = cnt[i];
        unsigned nxt = (i + 1 < NBUCK) ? cnt[i + 1] : 0u;
        if (s >= PRE && nxt < PRE) { sh_b1 = i; sh_need = PRE - (int)nxt; }
    }
    __syncthreads();
    int b1 = sh_b1;
    int need = sh_need;
    __syncthreads();

    // ---- pass 2: within bucket b1, histogram of next 12 bits ----
    for (int i = tid; i < NBUCK; i += 1024) cnt[i] = 0;
    __syncthreads();
    for (int it = 0; it < NIT; it++) {
        int a = it * 1024 + tid;
        unsigned bucket = 0xFFFFFFFFu;
        if (a < NA) {
            unsigned u = __float_as_uint(sc[a]);
            if ((int)(u >> 20) == b1) bucket = (u >> 8) & 0xFFFu;
        }
        unsigned mask = __match_any_sync(0xFFFFFFFFu, bucket);
        int leader = __ffs(mask) - 1;
        if (bucket != 0xFFFFFFFFu && lane == leader)
            atomicAdd(&cnt[bucket], (unsigned)__popc(mask));
    }
    __syncthreads();
    suffix_scan4096(cnt, tid);
#pragma unroll
    for (int k = 0; k < NBUCK / 1024; k++) {
        int i = tid + k * 1024;
        unsigned s = cnt[i];
        unsigned nxt = (i + 1 < NBUCK) ? cnt[i + 1] : 0u;
        if (s >= (unsigned)need && nxt < (unsigned)need) sh_b2 = i;
    }
    if (tid == 0) sh_count = 0;
    __syncthreads();
    unsigned P = ((unsigned)b1 << 12) | (unsigned)sh_b2;

    // ---- compact survivors into padded smem as 64-bit keys (warp-aggregated) ----
    for (int it = 0; it < NIT; it++) {
        int a = it * 1024 + tid;
        unsigned u = 0;
        bool keep = false;
        if (a < NA) {
            u = __float_as_uint(sc[a]);
            keep = ((u >> 8) >= P);
        }
        unsigned bm = __ballot_sync(0xFFFFFFFFu, keep);
        if (keep) {
            int leader = __ffs(bm) - 1;
            int base;
            if (lane == leader) base = atomicAdd(&sh_count, __popc(bm));
            base = __shfl_sync(bm, base, leader);
            int pos = base + __popc(bm & ((1u << lane) - 1u));
            if (pos < CAP)
                sbuf[PHYS(pos)] = ((unsigned long long)u << 32) | (unsigned)(~a);
        }
    }
    __syncthreads();
    int total = min(sh_count, CAP);
    for (int i = total + tid; i < CAP; i += 1024) sbuf[PHYS(i)] = 0ULL;
    __syncthreads();

    // ---- bitonic sort descending, register-fused, bank-conflict-free ----
    {
        int base = tid * 16;
        int pbase = 17 * tid;
        unsigned long long v[16];
#pragma unroll
        for (int e = 0; e < 16; e++) v[e] = sbuf[pbase + e];
#pragma unroll
        for (int k2 = 2; k2 <= 16; k2 <<= 1) {
#pragma unroll
            for (int j = k2 >> 1; j >= 1; j >>= 1) {
#pragma unroll
                for (int e = 0; e < 16; e++) {
                    int x = e ^ j;
                    if (x > e) {
                        bool d = (k2 == 16) ? ((base & 16) == 0)
                                            : ((e & k2) == 0);
                        CE64(v[e], v[x], d);
                    }
                }
            }
        }
#pragma unroll
        for (int e = 0; e < 16; e++) sbuf[pbase + e] = v[e];
    }
    __syncthreads();

    for (unsigned k = 32; k <= CAP; k <<= 1) {
        for (unsigned j = k >> 1; j >= 16; j >>= 1) {
            for (unsigned i = tid; i < CAP; i += 1024) {
                unsigned ixj = i ^ j;
                if (ixj > i) {
                    unsigned pi = PHYS(i), pj = PHYS(ixj);
                    unsigned long long va = sbuf[pi], vb = sbuf[pj];
                    bool d = ((i & k) == 0);
                    if (d ? (va < vb) : (va > vb)) {
                        sbuf[pi] = vb;
                        sbuf[pj] = va;
                    }
                }
            }
            __syncthreads();
        }
        {
            int base = tid * 16;
            int pbase = 17 * tid;
            bool d = (((unsigned)base & k) == 0);
            unsigned long long v[16];
#pragma unroll
            for (int e = 0; e < 16; e++) v[e] = sbuf[pbase + e];
#pragma unroll
            for (int j2 = 8; j2 >= 1; j2 >>= 1) {
#pragma unroll
                for (int e = 0; e < 16; e++) {
                    int x = e ^ j2;
                    if (x > e) CE64(v[e], v[x], d);
                }
            }
#pragma unroll
            for (int e = 0; e < 16; e++) sbuf[pbase + e] = v[e];
        }
        __syncthreads();
    }

    // ---- gather top PRE boxes ----
    const float4* bx = boxes + (size_t)b * NA;
    for (int r = tid; r < PRE; r += 1024) {
        unsigned a = ~(unsigned)(sbuf[PHYS(r)] & 0xFFFFFFFFu);
        g_sorted[b * PRE + r] = bx[a];
    }
}

// ---------------- exact area (reference arithmetic) ----------------
__device__ __forceinline__ float area_f(float4 a) {
    return __fmul_rn(__fsub_rn(a.z, a.x), __fsub_rn(a.w, a.y));
}

// ---------------- exact IoU decision with precomputed exact areas ----------------
// div_rn(inter/denom) > 0.7f <=> (double)inter >= (23488103/2^25)*(double)denom
// (25x24-bit f64 product exact; midpoint tie rounds to even successor > 0.7f).
__device__ __forceinline__ bool iou_gt2(float4 a, float aa, float4 b, float ab) {
    const double MID = 23488103.0 / 33554432.0;
    float iy1 = fmaxf(a.x, b.x);
    float ix1 = fmaxf(a.y, b.y);
    float iy2 = fminf(a.z, b.z);
    float ix2 = fminf(a.w, b.w);
    float ih = fmaxf(__fsub_rn(iy2, iy1), 0.f);
    float iw = fmaxf(__fsub_rn(ix2, ix1), 0.f);
    float inter = __fmul_rn(ih, iw);
    float denom = fmaxf(__fsub_rn(__fadd_rn(aa, ab), inter), 1e-8f);
    return (double)inter >= MID * (double)denom;
}

// Conservative prefilter: IoU <= min(A,B)/max(A,B). If min < 0.69*max, the
// reference's IoU cannot exceed 0.7f (1.4% margin >> fp noise) -> safe skip.
__device__ __forceinline__ bool area_pass(float aa, float ab) {
    return fminf(aa, ab) >= 0.69f * fmaxf(aa, ab);
}

// ---------------- K3: chunked lazy greedy NMS ----------------
// Selection function proven bit-identical to the literal transliteration.
// R16: parallel phase back to R13 mapping (candidate = lane, selected list
// strided by warp id -> uniform trip count, broadcast sel loads, NO intra-loop
// collectives) + area prefilter with cached areas (candarea/selarea).
__global__ void __launch_bounds__(1024, 1) nms_kernel(float* __restrict__ out) {
    const int b = blockIdx.x;
    const int tid = threadIdx.x;
    const int wid = tid >> 5;
    const int lane = tid & 31;
    const float4* sb = g_sorted + b * PRE;
    float* ob = out + (size_t)b * POST * 4;

    __shared__ float4 sel[POST];
    __shared__ float selarea[POST];
    __shared__ float4 cand[2][32];
    __shared__ float candarea[2][32];
    __shared__ unsigned supp_w[32];
    __shared__ int sh_nsel;

    if (tid < 32) {
        float4 c = sb[tid];
        cand[0][tid] = c;
        candarea[0][tid] = area_f(c);
    }
    if (tid == 0) sh_nsel = 0;
    __syncthreads();
    int nsel = 0;

    const int NCH = PRE / 32;  // 375, PRE % 32 == 0
    for (int ch = 0; ch < NCH && nsel < POST; ch++) {
        int cur = ch & 1, nxt = cur ^ 1;

        // prefetch next chunk + its areas (warp 1) — overlaps parallel phase
        if (wid == 1) {
            int j1 = (ch + 1) * 32;
            if (j1 < PRE) {
                float4 c = sb[j1 + lane];
                cand[nxt][lane] = c;
                candarea[nxt][lane] = area_f(c);
            }
        }

        // parallel phase: lane = candidate, warps stride the selected list.
        // sel[i]/selarea[i] are warp-broadcast loads (i uniform in warp).
        {
            float4 myc = cand[cur][lane];
            float mya = candarea[cur][lane];
            bool killed = false;
            for (int i = wid; i < nsel; i += 32) {
                float sa = selarea[i];
                if (!killed && area_pass(mya, sa) &&
                    iou_gt2(myc, mya, sel[i], sa))
                    killed = true;
            }
            unsigned kb = __ballot_sync(0xFFFFFFFFu, killed);
            if (lane == 0) supp_w[wid] = kb;
        }
        __syncthreads();

        // resolve phase (warp 0): OR the 32 warp slots, then pick/suppress
        if (tid < 32) {
            unsigned supp = __reduce_or_sync(0xFFFFFFFFu, supp_w[tid]);
            float4 myc = cand[cur][tid];
            float mya = candarea[cur][tid];
            unsigned live = ~supp;
            int ns = nsel;
            while (live != 0u && ns < POST) {
                int c = __ffs(live) - 1;
                float4 cb = cand[cur][c];        // smem broadcast
                float ca = candarea[cur][c];     // smem broadcast
                live &= ~(1u << c);
                bool kill = ((live >> tid) & 1u) && area_pass(mya, ca) &&
                            iou_gt2(myc, mya, cb, ca);
                live &= ~__ballot_sync(0xFFFFFFFFu, kill);
                if (tid == c) { sel[ns] = myc; selarea[ns] = mya; }
                ns++;
            }
            if (tid == 0) sh_nsel = ns;
        }
        __syncthreads();
        nsel = sh_nsel;
    }

    // final write-out: clamped selected rows, zeros after exhaustion
    for (int r = tid; r < POST; r += 1024) {
        float4 v = make_float4(0.f, 0.f, 0.f, 0.f);
        if (r < nsel) v = sel[r];
        v.x = fminf(fmaxf(v.x, 0.f), 1.f);
        v.y = fminf(fmaxf(v.y, 0.f), 1.f);
        v.z = fminf(fmaxf(v.z, 0.f), 1.f);
        v.w = fminf(fmaxf(v.w, 0.f), 1.f);
        reinterpret_cast<float4*>(ob)[r] = v;
    }
}

// ---------------- launcher ----------------
extern "C" void kernel_launch(void* const* d_in, const int* in_sizes, int n_in,
                              void* d_out, int out_size) {
    const float4* boxes = (const float4*)d_in[0];   // [B, A, 4] f32
    const float4* labels = (const float4*)d_in[1];  // [B, A, 4] f32
    float* out = (float*)d_out;                     // [B, POST, 4] f32

    size_t smem = (size_t)PCAP * 8 + (size_t)NBUCK * 4;
    cudaFuncSetAttribute(select_kernel, cudaFuncAttributeMaxDynamicSharedMemorySize,
                         (int)smem);

    score_kernel<<<(BATCH * NA + 255) / 256, 256>>>(labels);
    select_kernel<<<BATCH, 1024, smem>>>(boxes);
    nms_kernel<<<BATCH, 1024>>>(out);
}